// round 4
// baseline (speedup 1.0000x reference)
#include <cuda_runtime.h>
#include <cstdint>

// HexPool: out[i, :] = max_{k<7} x[neigh_indices[i,k], :]
// x: (655362, 64) f32 ; neigh_indices: (163842, 7) int32 ; out: (163842, 64) f32
//
// Shape: one thread per float4 of output -> 16 threads (one half-warp) per row.
// Gathered rows are 256B contiguous => perfectly coalesced LDG.128 per gather.
// Indices broadcast within the half-warp via one SHFL each (int32).
//
// Launch geometry: N_OUT = 2*3*7*47*83, so 14 rows/block (224 threads) divides
// exactly: grid = 11703, NO tail -> no clamp, no store predicate, every warp
// fully converged by construction.
//
// Bottleneck (measured R3): LTS bandwidth. 340 MB/launch through L2 at the
// ~6300 B/cyc chip cap => ~24 us floor. This round only shaves launch/ALU
// overhead; the traffic is algorithmic.

#define N_OUT 163842
#define KNB   7
#define VEC_PER_ROW 16      // 64 floats / 4
#define ROWS_PER_BLOCK 14
#define BLOCK_THREADS (ROWS_PER_BLOCK * VEC_PER_ROW)   // 224
#define GRID_BLOCKS (N_OUT / ROWS_PER_BLOCK)           // 11703 exact

__global__ __launch_bounds__(BLOCK_THREADS) void hexpool_kernel(
    const float4* __restrict__ x,          // viewed as [n_in][16] float4
    const int* __restrict__ idx,           // [N_OUT][7] int32
    float4* __restrict__ out)               // [N_OUT][16] float4
{
    const int gid = blockIdx.x * BLOCK_THREADS + threadIdx.x;
    const int row = gid >> 4;              // exact, never out of range
    const int col = gid & 15;

    const int lane = threadIdx.x & 31;
    const int half_base = lane & 16;       // 0 or 16: start lane of my half-warp
    const int sub = lane & 15;

    // Lanes sub<7 of each half-warp load the 7 indices for this half-warp's row.
    int my_idx = 0;
    if (sub < KNB) {
        my_idx = __ldg(&idx[row * KNB + sub]);
    }

    float4 m = make_float4(-3.402823466e+38f, -3.402823466e+38f,
                           -3.402823466e+38f, -3.402823466e+38f);

    #pragma unroll
    for (int k = 0; k < KNB; ++k) {
        int j = __shfl_sync(0xFFFFFFFFu, my_idx, half_base + k);
        float4 v = __ldg(&x[(long long)j * VEC_PER_ROW + col]);
        m.x = fmaxf(m.x, v.x);
        m.y = fmaxf(m.y, v.y);
        m.z = fmaxf(m.z, v.z);
        m.w = fmaxf(m.w, v.w);
    }

    out[gid] = m;
}

extern "C" void kernel_launch(void* const* d_in, const int* in_sizes, int n_in,
                              void* d_out, int out_size)
{
    const float4* x   = (const float4*)d_in[0];
    const int*    idx = (const int*)d_in[1];
    float4*       out = (float4*)d_out;

    hexpool_kernel<<<GRID_BLOCKS, BLOCK_THREADS>>>(x, idx, out);
}

// round 6
// speedup vs baseline: 1.0102x; 1.0102x over previous
#include <cuda_runtime.h>
#include <cstdint>

// HexPool: out[i, :] = max_{k<7} x[neigh_indices[i,k], :]
// x: (655362, 64) f32 ; neigh_indices: (163842, 7) int32 ; out: (163842, 64) f32
//
// Shape: 8 threads (one quarter-warp) per output row; each thread owns TWO
// float4 columns (c and c+8). Per thread: 14 independent gather LDG.128s in
// flight (2x the MLP of the 16-thread/row version), 7 SHFLs feeding 32B each.
// Per warp instruction: 4 rows x 128B contiguous segments -> fully coalesced.
//
// R5 bug fixed: 256 threads / 8 per row = 32 rows per block (was mislabeled 64,
// leaving half the output unwritten). grid = ceil(163842/32) = 5121.
// Tail block clamps row, predicates the store; all lanes stay converged
// through every __shfl_sync.

#define N_OUT 163842
#define KNB   7
#define VEC_PER_ROW 16      // 64 floats / 4
#define BLOCK_THREADS 256
#define ROWS_PER_BLOCK 32   // 256 threads / 8 threads per row

__device__ __forceinline__ void fmax4(float4& m, const float4& v) {
    m.x = fmaxf(m.x, v.x);
    m.y = fmaxf(m.y, v.y);
    m.z = fmaxf(m.z, v.z);
    m.w = fmaxf(m.w, v.w);
}

__global__ __launch_bounds__(BLOCK_THREADS) void hexpool_kernel(
    const float4* __restrict__ x,          // viewed as [n_in][16] float4
    const int* __restrict__ idx,           // [N_OUT][7] int32
    float4* __restrict__ out)               // [N_OUT][16] float4
{
    const int tid = blockIdx.x * BLOCK_THREADS + threadIdx.x;
    const int row_raw = tid >> 3;                    // 8 threads per row
    const int row = row_raw < N_OUT ? row_raw : (N_OUT - 1);
    const int col = tid & 7;                         // float4 col 0..7 (also owns col+8)

    const int lane = threadIdx.x & 31;
    const int q_base = lane & 24;                    // quarter-warp start lane
    const int sub = lane & 7;

    // Lanes sub<7 of each quarter-warp load the 7 indices for this row.
    int my_idx = 0;
    if (sub < KNB) {
        my_idx = __ldg(&idx[row * KNB + sub]);
    }

    const float NEG = -3.402823466e+38f;
    float4 m0 = make_float4(NEG, NEG, NEG, NEG);
    float4 m1 = make_float4(NEG, NEG, NEG, NEG);

    #pragma unroll
    for (int k = 0; k < KNB; ++k) {
        int j = __shfl_sync(0xFFFFFFFFu, my_idx, q_base + k);
        const float4* rowp = &x[(long long)j * VEC_PER_ROW];
        float4 v0 = __ldg(rowp + col);
        float4 v1 = __ldg(rowp + col + 8);
        fmax4(m0, v0);
        fmax4(m1, v1);
    }

    if (row_raw < N_OUT) {
        float4* orow = &out[(long long)row_raw * VEC_PER_ROW];
        orow[col]     = m0;
        orow[col + 8] = m1;
    }
}

extern "C" void kernel_launch(void* const* d_in, const int* in_sizes, int n_in,
                              void* d_out, int out_size)
{
    const float4* x   = (const float4*)d_in[0];
    const int*    idx = (const int*)d_in[1];
    float4*       out = (float4*)d_out;

    const int grid = (N_OUT + ROWS_PER_BLOCK - 1) / ROWS_PER_BLOCK;  // 5121
    hexpool_kernel<<<grid, BLOCK_THREADS>>>(x, idx, out);
}

// round 7
// speedup vs baseline: 1.1445x; 1.1329x over previous
#include <cuda_runtime.h>
#include <cstdint>

// HexPool: out[i, :] = max_{k<7} x[neigh_indices[i,k], :]
// x: (655362, 64) f32 ; neigh_indices: (163842, 7) int32 ; out: (163842, 64) f32
//
// Measured conclusion (R3/R4/R6): kernel is pinned at the B300 LTS achievable
// cap (~6300 B/cyc; ncu L2% ~49-50% of theoretical in every geometry).
// Traffic (~340 MB/launch) is algorithmically irreducible for uniform-random
// indices. Geometry: R3 shape was best (16 threads/row, 256-thread blocks).
//
// This round's only change vs R3: output stores use __stcs (evict-first) so
// the write-once output (42 MB) does not thrash the L2-resident gather region
// of x (42 MB) -> lower DRAM re-fetch of x across graph replays.

#define N_OUT 163842
#define KNB   7
#define VEC_PER_ROW 16   // 64 floats / 4

__global__ __launch_bounds__(256) void hexpool_kernel(
    const float4* __restrict__ x,          // viewed as [n_in][16] float4
    const int* __restrict__ idx,           // [N_OUT][7] int32
    float4* __restrict__ out)               // [N_OUT][16] float4
{
    const int gid = blockIdx.x * blockDim.x + threadIdx.x;
    const int row_raw = gid >> 4;                 // output row (may overshoot in tail)
    const int row = row_raw < N_OUT ? row_raw : (N_OUT - 1);
    const int col = gid & 15;                     // float4 column within row

    const int lane = threadIdx.x & 31;
    const int half_base = lane & 16;              // 0 or 16: start lane of my half-warp
    const int sub = lane & 15;

    // Lanes sub<7 of each half-warp load the 7 indices for this half-warp's row.
    int my_idx = 0;
    if (sub < KNB) {
        my_idx = __ldg(&idx[row * KNB + sub]);
    }

    float4 m = make_float4(-3.402823466e+38f, -3.402823466e+38f,
                           -3.402823466e+38f, -3.402823466e+38f);

    #pragma unroll
    for (int k = 0; k < KNB; ++k) {
        int j = __shfl_sync(0xFFFFFFFFu, my_idx, half_base + k);
        float4 v = __ldg(&x[(long long)j * VEC_PER_ROW + col]);
        m.x = fmaxf(m.x, v.x);
        m.y = fmaxf(m.y, v.y);
        m.z = fmaxf(m.z, v.z);
        m.w = fmaxf(m.w, v.w);
    }

    if (row_raw < N_OUT) {
        __stcs(&out[gid], m);   // evict-first: don't displace x's L2 lines
    }
}

extern "C" void kernel_launch(void* const* d_in, const int* in_sizes, int n_in,
                              void* d_out, int out_size)
{
    const float4* x   = (const float4*)d_in[0];
    const int*    idx = (const int*)d_in[1];
    float4*       out = (float4*)d_out;

    const int total_threads = N_OUT * VEC_PER_ROW;   // 2,621,472
    const int block = 256;
    const int grid  = (total_threads + block - 1) / block;
    hexpool_kernel<<<grid, block>>>(x, idx, out);
}